// round 10
// baseline (speedup 1.0000x reference)
#include <cuda_runtime.h>
#include <cuda_fp16.h>
#include <mma.h>

#define IN_DIM 128
#define HID 64
#define NNMAX 100000
#define NEMAX 3200000

using namespace nvcuda;

// ---------------- scratch (static device globals; no allocs allowed) -------
__device__ __align__(16) float  g_agg[NNMAX * HID];
__device__ __align__(16) __half g_h0h[NNMAX * HID];
__device__ __align__(16) __half g_h1h[NNMAX * HID];
__device__ int g_deg[NNMAX];
__device__ int g_off[NNMAX];
__device__ int g_cur[NNMAX];
__device__ int g_blk[512];
__device__ int g_srcs[NEMAX];
__device__ int g_is64;

// ---------------- zero + edge dtype sniff (fused) ---------------------------
__global__ void k_zs(const void* ei, int n, int nE) {
    int i = blockIdx.x * 256 + threadIdx.x;
    if (i < n) g_deg[i] = 0;
    if (blockIdx.x == 0 && threadIdx.x == 0) {
        const long long* e64 = (const long long*)ei;
        int ok = 1;
        int lim = (nE < 16) ? nE : 16;
        for (int k = 0; k < lim; k++) {
            long long v = e64[k];
            if (v < 0 || v >= (long long)n) { ok = 0; break; }
        }
        g_is64 = ok;
    }
}

// ---------------- graph preprocessing: counting sort by dst ----------------
__global__ void k_count(const void* __restrict__ ei, int n, int nE) {
    int e = blockIdx.x * 256 + threadIdx.x;
    if (e >= nE) return;
    int d;
    if (g_is64) d = (int)((const long long*)ei)[nE + e];
    else        d = ((const int*)ei)[nE + e];
    if ((unsigned)d < (unsigned)n) atomicAdd(&g_deg[d], 1);
}

__global__ void k_scan1(int n) {
    __shared__ int s[512];
    int tid = threadIdx.x;
    int i = blockIdx.x * 512 + tid;
    int v = (i < n) ? g_deg[i] : 0;
    s[tid] = v;
    __syncthreads();
    for (int o = 1; o < 512; o <<= 1) {
        int t = (tid >= o) ? s[tid - o] : 0;
        __syncthreads();
        s[tid] += t;
        __syncthreads();
    }
    if (i < n) g_off[i] = s[tid] - v;
    if (tid == 511) g_blk[blockIdx.x] = s[511];
}

__global__ void k_scan2(int nb) {
    __shared__ int s[512];
    int tid = threadIdx.x;
    int v = (tid < nb) ? g_blk[tid] : 0;
    s[tid] = v;
    __syncthreads();
    for (int o = 1; o < 512; o <<= 1) {
        int t = (tid >= o) ? s[tid - o] : 0;
        __syncthreads();
        s[tid] += t;
        __syncthreads();
    }
    if (tid < nb) g_blk[tid] = s[tid] - v;
}

__global__ void k_scan3(int n) {
    int i = blockIdx.x * 512 + threadIdx.x;
    if (i < n) {
        int o = g_off[i] + g_blk[blockIdx.x];
        g_off[i] = o;
        g_cur[i] = o;
    }
}

__global__ void k_bucket(const void* __restrict__ ei, int n, int nE) {
    int e = blockIdx.x * 256 + threadIdx.x;
    if (e >= nE) return;
    int d, s;
    if (g_is64) {
        d = (int)((const long long*)ei)[nE + e];
        s = (int)((const long long*)ei)[e];
    } else {
        d = ((const int*)ei)[nE + e];
        s = ((const int*)ei)[e];
    }
    if ((unsigned)d >= (unsigned)n || (unsigned)s >= (unsigned)n) return;
    int p = atomicAdd(&g_cur[d], 1);
    g_srcs[p] = s;
}

// ---------------- tensor-core GEMM (WMMA) -----------------------------------
// out = act([A0|A1] @ [W0;W1]^T + bias), K = 64+64, m16n16k16 HMMA.
// CTA: 128 rows x 64 cols, whole K staged in one 48 KB smem arena.
// 8 warps, each an m16 strip; A frags hoisted; 4 n-tiles x 8 k-steps.
// Epilogue: acc -> smem fp32, then bias(+relu)->fp16 store, or fused head.
__global__ void __launch_bounds__(256)
k_gemm(const float* __restrict__ A0f, const float* __restrict__ A1f,
       const __half* __restrict__ A1h,
       const float* __restrict__ W0, const float* __restrict__ W1,
       const float* __restrict__ bias,
       __half* __restrict__ outh, float* __restrict__ headout,
       const float* __restrict__ hw, const float* __restrict__ hb,
       int n, int ld, int dorelu) {
    __shared__ __align__(16) char SMEM[49152];
    __half* TA = (__half*)SMEM;              // 128 x 128 fp16, row-major
    __half* TW = (__half*)(SMEM + 32768);    // 64 cols x 128 k, col-major ld=128
    float*  OC = (float*)SMEM;               // epilogue: 128 x 64 fp32

    int tid = threadIdx.x;
    int row0 = blockIdx.x * 128;

    // W tile: element W(c, k) -> TW[c*128 + k]
    for (int ch = tid; ch < 1024; ch += 256) {
        int c = ch >> 4, c16 = ch & 15;
        int hf = c16 >> 3, k8 = (c16 & 7) * 8;
        const float* Wsrc = hf ? W1 : W0;
        float4 v0 = *(const float4*)&Wsrc[c * ld + k8];
        float4 v1 = *(const float4*)&Wsrc[c * ld + k8 + 4];
        union { __half2 h[4]; uint4 u; } pk;
        pk.h[0] = __floats2half2_rn(v0.x, v0.y);
        pk.h[1] = __floats2half2_rn(v0.z, v0.w);
        pk.h[2] = __floats2half2_rn(v1.x, v1.y);
        pk.h[3] = __floats2half2_rn(v1.z, v1.w);
        *(uint4*)&TW[c * 128 + c16 * 8] = pk.u;
    }
    // A tile: row gr, k = c16*8 .. +8
    for (int ch = tid; ch < 2048; ch += 256) {
        int r = ch >> 4, c16 = ch & 15;
        int hf = c16 >> 3, k8 = (c16 & 7) * 8;
        int gr = row0 + r;
        uint4 u = make_uint4(0u, 0u, 0u, 0u);
        if (gr < n) {
            if (hf == 0 || A1f) {
                const float* Asrc = hf ? A1f : A0f;
                float4 v0 = *(const float4*)&Asrc[gr * ld + k8];
                float4 v1 = *(const float4*)&Asrc[gr * ld + k8 + 4];
                union { __half2 h[4]; uint4 u; } pk;
                pk.h[0] = __floats2half2_rn(v0.x, v0.y);
                pk.h[1] = __floats2half2_rn(v0.z, v0.w);
                pk.h[2] = __floats2half2_rn(v1.x, v1.y);
                pk.h[3] = __floats2half2_rn(v1.z, v1.w);
                u = pk.u;
            } else {
                u = *(const uint4*)&A1h[gr * HID + k8];
            }
        }
        *(uint4*)&TA[r * 128 + c16 * 8] = u;
    }
    __syncthreads();

    int warp = tid >> 5;
    int m = warp * 16;

    wmma::fragment<wmma::matrix_a, 16, 16, 16, __half, wmma::row_major> fa[8];
#pragma unroll
    for (int ks = 0; ks < 8; ks++)
        wmma::load_matrix_sync(fa[ks], &TA[m * 128 + ks * 16], 128);

    wmma::fragment<wmma::accumulator, 16, 16, 16, float> fc[4];
#pragma unroll
    for (int nt = 0; nt < 4; nt++)
        wmma::fill_fragment(fc[nt], 0.0f);

#pragma unroll
    for (int nt = 0; nt < 4; nt++) {
#pragma unroll
        for (int ks = 0; ks < 8; ks++) {
            wmma::fragment<wmma::matrix_b, 16, 16, 16, __half, wmma::col_major> fb;
            wmma::load_matrix_sync(fb, &TW[nt * 16 * 128 + ks * 16], 128);
            wmma::mma_sync(fc[nt], fa[ks], fb, fc[nt]);
        }
    }

    // all warps done reading TA/TW before the arena is reused for fp32 out
    __syncthreads();
#pragma unroll
    for (int nt = 0; nt < 4; nt++)
        wmma::store_matrix_sync(&OC[m * 64 + nt * 16], fc[nt], 64,
                                wmma::mem_row_major);
    __syncthreads();

    if (headout) {
        float hb0 = __ldg(hb);
        for (int r = tid; r < 128; r += 256) {
            int gr = row0 + r;
            if (gr >= n) continue;
            float s = 0.f;
            for (int c = 0; c < HID; c++)
                s += (OC[r * 64 + c] + __ldg(&bias[c])) * __ldg(&hw[c]);
            headout[gr] = s + hb0;
        }
    } else {
        for (int idx = tid; idx < 128 * 16; idx += 256) {
            int r = idx >> 4, cg = idx & 15;
            int gr = row0 + r;
            if (gr >= n) continue;
            float4 v = *(const float4*)&OC[r * 64 + cg * 4];
            float4 b = *(const float4*)&bias[cg * 4];
            float f0 = v.x + b.x, f1 = v.y + b.y;
            float f2 = v.z + b.z, f3 = v.w + b.w;
            if (dorelu) {
                f0 = fmaxf(f0, 0.f); f1 = fmaxf(f1, 0.f);
                f2 = fmaxf(f2, 0.f); f3 = fmaxf(f3, 0.f);
            }
            union { __half2 h[2]; uint2 u; } pk;
            pk.h[0] = __floats2half2_rn(f0, f1);
            pk.h[1] = __floats2half2_rn(f2, f3);
            *(uint2*)&outh[gr * HID + cg * 4] = pk.u;
        }
    }
}

// ---------------- mean aggregation: warp per node, fp16 CSR pull ------------
__global__ void k_agg(int which, int n) {
    int node = blockIdx.x * 8 + (threadIdx.x >> 5);
    if (node >= n) return;
    const __half* __restrict__ hin = which ? g_h1h : g_h0h;
    int lane = threadIdx.x & 31;
    int grp = lane >> 3, sub = lane & 7;
    int st = g_off[node];
    int d  = g_deg[node];
    float a[8] = {};

    int j = 0;
    for (; j + 4 <= d; j += 4) {
        int e = g_srcs[st + j + grp];
        uint4 v = *(const uint4*)&hin[e * HID + sub * 8];
        const __half2* hp = (const __half2*)&v;
#pragma unroll
        for (int q = 0; q < 4; q++) {
            float2 f = __half22float2(hp[q]);
            a[2 * q]     += f.x;
            a[2 * q + 1] += f.y;
        }
    }
    if (j + grp < d) {
        int e = g_srcs[st + j + grp];
        uint4 v = *(const uint4*)&hin[e * HID + sub * 8];
        const __half2* hp = (const __half2*)&v;
#pragma unroll
        for (int q = 0; q < 4; q++) {
            float2 f = __half22float2(hp[q]);
            a[2 * q]     += f.x;
            a[2 * q + 1] += f.y;
        }
    }

#pragma unroll
    for (int q = 0; q < 8; q++) {
        a[q] += __shfl_xor_sync(0xffffffffu, a[q], 8);
        a[q] += __shfl_xor_sync(0xffffffffu, a[q], 16);
    }

    if (grp == 0) {
        float inv = 1.f / fmaxf((float)d, 1.f);
        float4 o0 = make_float4(a[0] * inv, a[1] * inv, a[2] * inv, a[3] * inv);
        float4 o1 = make_float4(a[4] * inv, a[5] * inv, a[6] * inv, a[7] * inv);
        *(float4*)&g_agg[node * HID + sub * 8]     = o0;
        *(float4*)&g_agg[node * HID + sub * 8 + 4] = o1;
    }
}

// ---------------- launch ----------------------------------------------------
extern "C" void kernel_launch(void* const* d_in, const int* in_sizes, int n_in,
                              void* d_out, int out_size) {
    const float* x   = (const float*)d_in[0];
    const void*  ei  = d_in[1];
    const float* fcW = (const float*)d_in[3];
    const float* fcb = (const float*)d_in[4];
    const float* Wl1 = (const float*)d_in[5];
    const float* bl1 = (const float*)d_in[6];
    const float* Wr1 = (const float*)d_in[7];
    const float* Wl2 = (const float*)d_in[8];
    const float* bl2 = (const float*)d_in[9];
    const float* Wr2 = (const float*)d_in[10];
    const float* hW  = (const float*)d_in[11];
    const float* hb  = (const float*)d_in[12];

    int n  = in_sizes[0] / IN_DIM;
    int nE = in_sizes[1] / 2;
    float* out = (float*)d_out;

    float*  agg;  cudaGetSymbolAddress((void**)&agg, g_agg);
    __half* h0h;  cudaGetSymbolAddress((void**)&h0h, g_h0h);
    __half* h1h;  cudaGetSymbolAddress((void**)&h1h, g_h1h);

    int gbN  = (n + 255) / 256;
    int gbE  = (nE + 255) / 256;
    int nblk = (n + 511) / 512;
    int gbG  = (n + 127) / 128;
    int gbW  = (n + 7) / 8;

    k_zs    <<<gbN, 256>>>(ei, n, nE);
    k_count <<<gbE, 256>>>(ei, n, nE);
    k_scan1 <<<nblk, 512>>>(n);
    k_gemm  <<<gbG, 256>>>(x, x + 64, (const __half*)0,
                           fcW, fcW + 64, fcb,
                           h0h, (float*)0, hW, hb,
                           n, IN_DIM, 1);
    k_scan2 <<<1, 512>>>(nblk);
    k_scan3 <<<nblk, 512>>>(n);
    k_bucket<<<gbE, 256>>>(ei, n, nE);

    k_agg  <<<gbW, 256>>>(0, n);
    k_gemm <<<gbG, 256>>>(agg, (const float*)0, h0h,
                          Wl1, Wr1, bl1,
                          h1h, (float*)0, hW, hb,
                          n, HID, 1);
    k_agg  <<<gbW, 256>>>(1, n);
    k_gemm <<<gbG, 256>>>(agg, (const float*)0, h1h,
                          Wl2, Wr2, bl2,
                          (__half*)0, out, hW, hb,
                          n, HID, 0);
}

// round 12
// speedup vs baseline: 1.4274x; 1.4274x over previous
#include <cuda_runtime.h>
#include <cuda_fp16.h>
#include <mma.h>

#define IN_DIM 128
#define HID 64
#define NNMAX 100000
#define NEMAX 3200000

using namespace nvcuda;

// ---------------- scratch (static device globals; no allocs allowed) -------
__device__ __align__(16) float  g_agg[NNMAX * HID];
__device__ __align__(16) __half g_h0h[NNMAX * HID];
__device__ __align__(16) __half g_h1h[NNMAX * HID];
__device__ int g_deg[NNMAX];
__device__ int g_off[NNMAX];
__device__ int g_cur[NNMAX];
__device__ int g_blk[512];
__device__ int g_srcs[NEMAX];
__device__ int g_is64;

// ---------------- zero + edge dtype sniff (fused) ---------------------------
__global__ void k_zs(const void* ei, int n, int nE) {
    int i = blockIdx.x * 256 + threadIdx.x;
    if (i < n) g_deg[i] = 0;
    if (blockIdx.x == 0 && threadIdx.x == 0) {
        const long long* e64 = (const long long*)ei;
        int ok = 1;
        int lim = (nE < 16) ? nE : 16;
        for (int k = 0; k < lim; k++) {
            long long v = e64[k];
            if (v < 0 || v >= (long long)n) { ok = 0; break; }
        }
        g_is64 = ok;
    }
}

// ---------------- graph preprocessing: counting sort by dst ----------------
__global__ void k_count(const void* __restrict__ ei, int n, int nE) {
    int e = blockIdx.x * 256 + threadIdx.x;
    if (e >= nE) return;
    int d;
    if (g_is64) d = (int)((const long long*)ei)[nE + e];
    else        d = ((const int*)ei)[nE + e];
    if ((unsigned)d < (unsigned)n) atomicAdd(&g_deg[d], 1);
}

__global__ void k_scan1(int n) {
    __shared__ int s[512];
    int tid = threadIdx.x;
    int i = blockIdx.x * 512 + tid;
    int v = (i < n) ? g_deg[i] : 0;
    s[tid] = v;
    __syncthreads();
    for (int o = 1; o < 512; o <<= 1) {
        int t = (tid >= o) ? s[tid - o] : 0;
        __syncthreads();
        s[tid] += t;
        __syncthreads();
    }
    if (i < n) g_off[i] = s[tid] - v;
    if (tid == 511) g_blk[blockIdx.x] = s[511];
}

__global__ void k_scan2(int nb) {
    __shared__ int s[512];
    int tid = threadIdx.x;
    int v = (tid < nb) ? g_blk[tid] : 0;
    s[tid] = v;
    __syncthreads();
    for (int o = 1; o < 512; o <<= 1) {
        int t = (tid >= o) ? s[tid - o] : 0;
        __syncthreads();
        s[tid] += t;
        __syncthreads();
    }
    if (tid < nb) g_blk[tid] = s[tid] - v;
}

__global__ void k_scan3(int n) {
    int i = blockIdx.x * 512 + threadIdx.x;
    if (i < n) {
        int o = g_off[i] + g_blk[blockIdx.x];
        g_off[i] = o;
        g_cur[i] = o;
    }
}

__global__ void k_bucket(const void* __restrict__ ei, int n, int nE) {
    int e = blockIdx.x * 256 + threadIdx.x;
    if (e >= nE) return;
    int d, s;
    if (g_is64) {
        d = (int)((const long long*)ei)[nE + e];
        s = (int)((const long long*)ei)[e];
    } else {
        d = ((const int*)ei)[nE + e];
        s = ((const int*)ei)[e];
    }
    if ((unsigned)d >= (unsigned)n || (unsigned)s >= (unsigned)n) return;
    int p = atomicAdd(&g_cur[d], 1);
    g_srcs[p] = s;
}

// ---------------- tensor-core GEMM (WMMA, padded tiles) ---------------------
// out = act([A0|A1] @ [W0;W1]^T + bias) via m16n16k16 HMMA, fp32 accum.
// Two K-stages of 64. ALL source pointers are PRE-OFFSET by the caller:
// the loader always reads k8 in [0,64) from the stage's pointer.
// Tiles padded (ld=72 halfs / 68 floats) -> conflict-free ldmatrix/stores.
// One 35 KB arena: stage tiles (27.6 KB) overlaid with fp32 epilogue (34.8 KB).
#define TA_LD 72
#define TW_LD 72
#define OC_LD 68

__global__ void __launch_bounds__(256)
k_gemm(const float* __restrict__ A0f, const float* __restrict__ A1f,
       const __half* __restrict__ A1h,
       const float* __restrict__ W0, const float* __restrict__ W1,
       const float* __restrict__ bias,
       __half* __restrict__ outh, float* __restrict__ headout,
       const float* __restrict__ hw, const float* __restrict__ hb,
       int n, int ld, int dorelu) {
    __shared__ __align__(16) char SMEM[128 * OC_LD * 4];
    __half* TA = (__half*)SMEM;                          // 128 x 72 halfs
    __half* TW = (__half*)(SMEM + 128 * TA_LD * 2);      // 64 x 72 halfs
    float*  OC = (float*)SMEM;                           // 128 x 68 floats

    int tid = threadIdx.x;
    int row0 = blockIdx.x * 128;
    int warp = tid >> 5;
    int m = warp * 16;

    wmma::fragment<wmma::accumulator, 16, 16, 16, float> fc[4];
#pragma unroll
    for (int nt = 0; nt < 4; nt++)
        wmma::fill_fragment(fc[nt], 0.0f);

    for (int s = 0; s < 2; s++) {
        // W slab: 64 cols x 64 k -> 512 16B chunks (pointer pre-offset)
        for (int ch = tid; ch < 512; ch += 256) {
            int c = ch >> 3, k8 = (ch & 7) * 8;
            const float* Wsrc = s ? W1 : W0;
            float4 v0 = *(const float4*)&Wsrc[c * ld + k8];
            float4 v1 = *(const float4*)&Wsrc[c * ld + k8 + 4];
            union { __half2 h[4]; uint4 u; } pk;
            pk.h[0] = __floats2half2_rn(v0.x, v0.y);
            pk.h[1] = __floats2half2_rn(v0.z, v0.w);
            pk.h[2] = __floats2half2_rn(v1.x, v1.y);
            pk.h[3] = __floats2half2_rn(v1.z, v1.w);
            *(uint4*)&TW[c * TW_LD + k8] = pk.u;
        }
        // A slab: 128 rows x 64 k -> 1024 chunks (pointer pre-offset)
        for (int ch = tid; ch < 1024; ch += 256) {
            int r = ch >> 3, k8 = (ch & 7) * 8;
            int gr = row0 + r;
            uint4 u = make_uint4(0u, 0u, 0u, 0u);
            if (gr < n) {
                if (s == 0 || A1f) {
                    const float* Asrc = s ? A1f : A0f;
                    float4 v0 = *(const float4*)&Asrc[gr * ld + k8];
                    float4 v1 = *(const float4*)&Asrc[gr * ld + k8 + 4];
                    union { __half2 h[4]; uint4 u; } pk;
                    pk.h[0] = __floats2half2_rn(v0.x, v0.y);
                    pk.h[1] = __floats2half2_rn(v0.z, v0.w);
                    pk.h[2] = __floats2half2_rn(v1.x, v1.y);
                    pk.h[3] = __floats2half2_rn(v1.z, v1.w);
                    u = pk.u;
                } else {
                    u = *(const uint4*)&A1h[gr * HID + k8];
                }
            }
            *(uint4*)&TA[r * TA_LD + k8] = u;
        }
        __syncthreads();

        wmma::fragment<wmma::matrix_a, 16, 16, 16, __half, wmma::row_major> fa[4];
#pragma unroll
        for (int ks = 0; ks < 4; ks++)
            wmma::load_matrix_sync(fa[ks], &TA[m * TA_LD + ks * 16], TA_LD);

#pragma unroll
        for (int nt = 0; nt < 4; nt++) {
#pragma unroll
            for (int ks = 0; ks < 4; ks++) {
                wmma::fragment<wmma::matrix_b, 16, 16, 16, __half,
                               wmma::col_major> fb;
                wmma::load_matrix_sync(fb, &TW[nt * 16 * TW_LD + ks * 16], TW_LD);
                wmma::mma_sync(fc[nt], fa[ks], fb, fc[nt]);
            }
        }
        __syncthreads();   // tiles free before next stage / epilogue overlay
    }

#pragma unroll
    for (int nt = 0; nt < 4; nt++)
        wmma::store_matrix_sync(&OC[m * OC_LD + nt * 16], fc[nt], OC_LD,
                                wmma::mem_row_major);
    __syncthreads();

    if (headout) {
        float hb0 = __ldg(hb);
        for (int r = tid; r < 128; r += 256) {
            int gr = row0 + r;
            if (gr >= n) continue;
            float s = 0.f;
            for (int c = 0; c < HID; c++)
                s += (OC[r * OC_LD + c] + __ldg(&bias[c])) * __ldg(&hw[c]);
            headout[gr] = s + hb0;
        }
    } else {
        for (int idx = tid; idx < 128 * 16; idx += 256) {
            int r = idx >> 4, cg = idx & 15;
            int gr = row0 + r;
            if (gr >= n) continue;
            float4 v = *(const float4*)&OC[r * OC_LD + cg * 4];
            float4 b = *(const float4*)&bias[cg * 4];
            float f0 = v.x + b.x, f1 = v.y + b.y;
            float f2 = v.z + b.z, f3 = v.w + b.w;
            if (dorelu) {
                f0 = fmaxf(f0, 0.f); f1 = fmaxf(f1, 0.f);
                f2 = fmaxf(f2, 0.f); f3 = fmaxf(f3, 0.f);
            }
            union { __half2 h[2]; uint2 u; } pk;
            pk.h[0] = __floats2half2_rn(f0, f1);
            pk.h[1] = __floats2half2_rn(f2, f3);
            *(uint2*)&outh[gr * HID + cg * 4] = pk.u;
        }
    }
}

// ---------------- mean aggregation: warp per node, fp16 CSR pull ------------
__global__ void k_agg(int which, int n) {
    int node = blockIdx.x * 8 + (threadIdx.x >> 5);
    if (node >= n) return;
    const __half* __restrict__ hin = which ? g_h1h : g_h0h;
    int lane = threadIdx.x & 31;
    int grp = lane >> 3, sub = lane & 7;
    int st = g_off[node];
    int d  = g_deg[node];
    float a[8] = {};

    int j = 0;
    for (; j + 4 <= d; j += 4) {
        int e = g_srcs[st + j + grp];
        uint4 v = *(const uint4*)&hin[e * HID + sub * 8];
        const __half2* hp = (const __half2*)&v;
#pragma unroll
        for (int q = 0; q < 4; q++) {
            float2 f = __half22float2(hp[q]);
            a[2 * q]     += f.x;
            a[2 * q + 1] += f.y;
        }
    }
    if (j + grp < d) {
        int e = g_srcs[st + j + grp];
        uint4 v = *(const uint4*)&hin[e * HID + sub * 8];
        const __half2* hp = (const __half2*)&v;
#pragma unroll
        for (int q = 0; q < 4; q++) {
            float2 f = __half22float2(hp[q]);
            a[2 * q]     += f.x;
            a[2 * q + 1] += f.y;
        }
    }

#pragma unroll
    for (int q = 0; q < 8; q++) {
        a[q] += __shfl_xor_sync(0xffffffffu, a[q], 8);
        a[q] += __shfl_xor_sync(0xffffffffu, a[q], 16);
    }

    if (grp == 0) {
        float inv = 1.f / fmaxf((float)d, 1.f);
        float4 o0 = make_float4(a[0] * inv, a[1] * inv, a[2] * inv, a[3] * inv);
        float4 o1 = make_float4(a[4] * inv, a[5] * inv, a[6] * inv, a[7] * inv);
        *(float4*)&g_agg[node * HID + sub * 8]     = o0;
        *(float4*)&g_agg[node * HID + sub * 8 + 4] = o1;
    }
}

// ---------------- launch ----------------------------------------------------
extern "C" void kernel_launch(void* const* d_in, const int* in_sizes, int n_in,
                              void* d_out, int out_size) {
    const float* x   = (const float*)d_in[0];
    const void*  ei  = d_in[1];
    const float* fcW = (const float*)d_in[3];
    const float* fcb = (const float*)d_in[4];
    const float* Wl1 = (const float*)d_in[5];
    const float* bl1 = (const float*)d_in[6];
    const float* Wr1 = (const float*)d_in[7];
    const float* Wl2 = (const float*)d_in[8];
    const float* bl2 = (const float*)d_in[9];
    const float* Wr2 = (const float*)d_in[10];
    const float* hW  = (const float*)d_in[11];
    const float* hb  = (const float*)d_in[12];

    int n  = in_sizes[0] / IN_DIM;
    int nE = in_sizes[1] / 2;
    float* out = (float*)d_out;

    float*  agg;  cudaGetSymbolAddress((void**)&agg, g_agg);
    __half* h0h;  cudaGetSymbolAddress((void**)&h0h, g_h0h);
    __half* h1h;  cudaGetSymbolAddress((void**)&h1h, g_h1h);

    int gbN  = (n + 255) / 256;
    int gbE  = (nE + 255) / 256;
    int nblk = (n + 511) / 512;
    int gbG  = (n + 127) / 128;
    int gbW  = (n + 7) / 8;

    k_zs    <<<gbN, 256>>>(ei, n, nE);
    k_count <<<gbE, 256>>>(ei, n, nE);
    k_scan1 <<<nblk, 512>>>(n);
    // fc: stage0 = (x, fcW), stage1 = (x+64, fcW+64); loader adds no koff.
    k_gemm  <<<gbG, 256>>>(x, x + 64, (const __half*)0,
                           fcW, fcW + 64, fcb,
                           h0h, (float*)0, hW, hb,
                           n, IN_DIM, 1);
    k_scan2 <<<1, 512>>>(nblk);
    k_scan3 <<<nblk, 512>>>(n);
    k_bucket<<<gbE, 256>>>(ei, n, nE);

    k_agg  <<<gbW, 256>>>(0, n);
    k_gemm <<<gbG, 256>>>(agg, (const float*)0, h0h,
                          Wl1, Wr1, bl1,
                          h1h, (float*)0, hW, hb,
                          n, HID, 1);
    k_agg  <<<gbW, 256>>>(1, n);
    k_gemm <<<gbG, 256>>>(agg, (const float*)0, h1h,
                          Wl2, Wr2, bl2,
                          (__half*)0, out, hW, hb,
                          n, HID, 0);
}

// round 13
// speedup vs baseline: 1.5448x; 1.0822x over previous
#include <cuda_runtime.h>
#include <cuda_fp16.h>
#include <mma.h>

#define IN_DIM 128
#define HID 64
#define NNMAX 100000
#define NEMAX 3200000

using namespace nvcuda;

// ---------------- scratch (static device globals; no allocs allowed) -------
__device__ __align__(16) __half g_aggh[NNMAX * HID];
__device__ __align__(16) __half g_h0h[NNMAX * HID];
__device__ __align__(16) __half g_h1h[NNMAX * HID];
__device__ int g_deg[NNMAX];
__device__ int g_off[NNMAX];
__device__ int g_cur[NNMAX];
__device__ int g_blk[512];
__device__ int g_srcs[NEMAX];
__device__ int g_is64;

// ---------------- zero + edge dtype sniff (fused) ---------------------------
__global__ void k_zs(const void* ei, int n, int nE) {
    int i = blockIdx.x * 256 + threadIdx.x;
    if (i < n) g_deg[i] = 0;
    if (blockIdx.x == 0 && threadIdx.x == 0) {
        const long long* e64 = (const long long*)ei;
        int ok = 1;
        int lim = (nE < 16) ? nE : 16;
        for (int k = 0; k < lim; k++) {
            long long v = e64[k];
            if (v < 0 || v >= (long long)n) { ok = 0; break; }
        }
        g_is64 = ok;
    }
}

// ---------------- graph preprocessing: counting sort by dst ----------------
__global__ void k_count(const void* __restrict__ ei, int n, int nE) {
    int e = blockIdx.x * 256 + threadIdx.x;
    if (e >= nE) return;
    int d;
    if (g_is64) d = (int)((const long long*)ei)[nE + e];
    else        d = ((const int*)ei)[nE + e];
    if ((unsigned)d < (unsigned)n) atomicAdd(&g_deg[d], 1);
}

__global__ void k_scan1(int n) {
    __shared__ int s[512];
    int tid = threadIdx.x;
    int i = blockIdx.x * 512 + tid;
    int v = (i < n) ? g_deg[i] : 0;
    s[tid] = v;
    __syncthreads();
    for (int o = 1; o < 512; o <<= 1) {
        int t = (tid >= o) ? s[tid - o] : 0;
        __syncthreads();
        s[tid] += t;
        __syncthreads();
    }
    if (i < n) g_off[i] = s[tid] - v;
    if (tid == 511) g_blk[blockIdx.x] = s[511];
}

__global__ void k_scan2(int nb) {
    __shared__ int s[512];
    int tid = threadIdx.x;
    int v = (tid < nb) ? g_blk[tid] : 0;
    s[tid] = v;
    __syncthreads();
    for (int o = 1; o < 512; o <<= 1) {
        int t = (tid >= o) ? s[tid - o] : 0;
        __syncthreads();
        s[tid] += t;
        __syncthreads();
    }
    if (tid < nb) g_blk[tid] = s[tid] - v;
}

__global__ void k_scan3(int n) {
    int i = blockIdx.x * 512 + threadIdx.x;
    if (i < n) {
        int o = g_off[i] + g_blk[blockIdx.x];
        g_off[i] = o;
        g_cur[i] = o;
    }
}

__global__ void k_bucket(const void* __restrict__ ei, int n, int nE) {
    int e = blockIdx.x * 256 + threadIdx.x;
    if (e >= nE) return;
    int d, s;
    if (g_is64) {
        d = (int)((const long long*)ei)[nE + e];
        s = (int)((const long long*)ei)[e];
    } else {
        d = ((const int*)ei)[nE + e];
        s = ((const int*)ei)[e];
    }
    if ((unsigned)d >= (unsigned)n || (unsigned)s >= (unsigned)n) return;
    int p = atomicAdd(&g_cur[d], 1);
    g_srcs[p] = s;
}

// ---------------- tensor-core GEMM (WMMA, padded tiles) ---------------------
// out = act([A0|A1] @ [W0;W1]^T + bias) via m16n16k16 HMMA, fp32 accum.
// Two K-stages of 64; all pointers pre-offset (loader reads k8 in [0,64)).
// fc: A0f/A1f fp32 (ld=IN_DIM). sage: A0h=agg fp16, A1h=h fp16 (ld=HID).
// Padded tiles (72 halfs / 68 floats) -> conflict-free ldmatrix/stores.
#define TA_LD 72
#define TW_LD 72
#define OC_LD 68

__global__ void __launch_bounds__(256)
k_gemm(const float* __restrict__ A0f, const float* __restrict__ A1f,
       const __half* __restrict__ A0h, const __half* __restrict__ A1h,
       const float* __restrict__ W0, const float* __restrict__ W1,
       const float* __restrict__ bias,
       __half* __restrict__ outh, float* __restrict__ headout,
       const float* __restrict__ hw, const float* __restrict__ hb,
       int n, int ld, int dorelu) {
    __shared__ __align__(16) char SMEM[128 * OC_LD * 4];
    __half* TA = (__half*)SMEM;                          // 128 x 72 halfs
    __half* TW = (__half*)(SMEM + 128 * TA_LD * 2);      // 64 x 72 halfs
    float*  OC = (float*)SMEM;                           // 128 x 68 floats

    int tid = threadIdx.x;
    int row0 = blockIdx.x * 128;
    int warp = tid >> 5;
    int m = warp * 16;

    wmma::fragment<wmma::accumulator, 16, 16, 16, float> fc[4];
#pragma unroll
    for (int nt = 0; nt < 4; nt++)
        wmma::fill_fragment(fc[nt], 0.0f);

    for (int s = 0; s < 2; s++) {
        // W slab: 64 cols x 64 k -> 512 16B chunks
        for (int ch = tid; ch < 512; ch += 256) {
            int c = ch >> 3, k8 = (ch & 7) * 8;
            const float* Wsrc = s ? W1 : W0;
            float4 v0 = *(const float4*)&Wsrc[c * ld + k8];
            float4 v1 = *(const float4*)&Wsrc[c * ld + k8 + 4];
            union { __half2 h[4]; uint4 u; } pk;
            pk.h[0] = __floats2half2_rn(v0.x, v0.y);
            pk.h[1] = __floats2half2_rn(v0.z, v0.w);
            pk.h[2] = __floats2half2_rn(v1.x, v1.y);
            pk.h[3] = __floats2half2_rn(v1.z, v1.w);
            *(uint4*)&TW[c * TW_LD + k8] = pk.u;
        }
        // A slab: 128 rows x 64 k -> 1024 chunks
        for (int ch = tid; ch < 1024; ch += 256) {
            int r = ch >> 3, k8 = (ch & 7) * 8;
            int gr = row0 + r;
            uint4 u = make_uint4(0u, 0u, 0u, 0u);
            if (gr < n) {
                if (A0f) {        // fp32 source (fc)
                    const float* Asrc = s ? A1f : A0f;
                    float4 v0 = *(const float4*)&Asrc[gr * ld + k8];
                    float4 v1 = *(const float4*)&Asrc[gr * ld + k8 + 4];
                    union { __half2 h[4]; uint4 u; } pk;
                    pk.h[0] = __floats2half2_rn(v0.x, v0.y);
                    pk.h[1] = __floats2half2_rn(v0.z, v0.w);
                    pk.h[2] = __floats2half2_rn(v1.x, v1.y);
                    pk.h[3] = __floats2half2_rn(v1.z, v1.w);
                    u = pk.u;
                } else {          // fp16 source (sage)
                    const __half* Asrc = s ? A1h : A0h;
                    u = *(const uint4*)&Asrc[gr * HID + k8];
                }
            }
            *(uint4*)&TA[r * TA_LD + k8] = u;
        }
        __syncthreads();

        wmma::fragment<wmma::matrix_a, 16, 16, 16, __half, wmma::row_major> fa[4];
#pragma unroll
        for (int ks = 0; ks < 4; ks++)
            wmma::load_matrix_sync(fa[ks], &TA[m * TA_LD + ks * 16], TA_LD);

#pragma unroll
        for (int nt = 0; nt < 4; nt++) {
#pragma unroll
            for (int ks = 0; ks < 4; ks++) {
                wmma::fragment<wmma::matrix_b, 16, 16, 16, __half,
                               wmma::col_major> fb;
                wmma::load_matrix_sync(fb, &TW[nt * 16 * TW_LD + ks * 16], TW_LD);
                wmma::mma_sync(fc[nt], fa[ks], fb, fc[nt]);
            }
        }
        __syncthreads();
    }

#pragma unroll
    for (int nt = 0; nt < 4; nt++)
        wmma::store_matrix_sync(&OC[m * OC_LD + nt * 16], fc[nt], OC_LD,
                                wmma::mem_row_major);
    __syncthreads();

    if (headout) {
        float hb0 = __ldg(hb);
        for (int r = tid; r < 128; r += 256) {
            int gr = row0 + r;
            if (gr >= n) continue;
            float s = 0.f;
            for (int c = 0; c < HID; c++)
                s += (OC[r * OC_LD + c] + __ldg(&bias[c])) * __ldg(&hw[c]);
            headout[gr] = s + hb0;
        }
    } else {
        for (int idx = tid; idx < 128 * 16; idx += 256) {
            int r = idx >> 4, cg = idx & 15;
            int gr = row0 + r;
            if (gr >= n) continue;
            float4 v = *(const float4*)&OC[r * OC_LD + cg * 4];
            float4 b = *(const float4*)&bias[cg * 4];
            float f0 = v.x + b.x, f1 = v.y + b.y;
            float f2 = v.z + b.z, f3 = v.w + b.w;
            if (dorelu) {
                f0 = fmaxf(f0, 0.f); f1 = fmaxf(f1, 0.f);
                f2 = fmaxf(f2, 0.f); f3 = fmaxf(f3, 0.f);
            }
            union { __half2 h[2]; uint2 u; } pk;
            pk.h[0] = __floats2half2_rn(f0, f1);
            pk.h[1] = __floats2half2_rn(f2, f3);
            *(uint2*)&outh[gr * HID + cg * 4] = pk.u;
        }
    }
}

// ---------------- mean aggregation: warp per node, fp16 CSR pull ------------
// 4 groups of 8 lanes; main loop pulls 2 edges/group (8/warp) for MLP.
// Output fp16 to g_aggh.
__global__ void k_agg(int which, int n) {
    int node = blockIdx.x * 8 + (threadIdx.x >> 5);
    if (node >= n) return;
    const __half* __restrict__ hin = which ? g_h1h : g_h0h;
    int lane = threadIdx.x & 31;
    int grp = lane >> 3, sub = lane & 7;
    int st = g_off[node];
    int d  = g_deg[node];
    float a[8] = {};

    int j = 0;
    for (; j + 8 <= d; j += 8) {
        int e0 = g_srcs[st + j + grp];
        int e1 = g_srcs[st + j + 4 + grp];
        uint4 v0 = *(const uint4*)&hin[e0 * HID + sub * 8];
        uint4 v1 = *(const uint4*)&hin[e1 * HID + sub * 8];
        const __half2* p0 = (const __half2*)&v0;
        const __half2* p1 = (const __half2*)&v1;
#pragma unroll
        for (int q = 0; q < 4; q++) {
            float2 f0 = __half22float2(p0[q]);
            float2 f1 = __half22float2(p1[q]);
            a[2 * q]     += f0.x + f1.x;
            a[2 * q + 1] += f0.y + f1.y;
        }
    }
    for (; j + 4 <= d; j += 4) {
        int e = g_srcs[st + j + grp];
        uint4 v = *(const uint4*)&hin[e * HID + sub * 8];
        const __half2* hp = (const __half2*)&v;
#pragma unroll
        for (int q = 0; q < 4; q++) {
            float2 f = __half22float2(hp[q]);
            a[2 * q]     += f.x;
            a[2 * q + 1] += f.y;
        }
    }
    if (j + grp < d) {
        int e = g_srcs[st + j + grp];
        uint4 v = *(const uint4*)&hin[e * HID + sub * 8];
        const __half2* hp = (const __half2*)&v;
#pragma unroll
        for (int q = 0; q < 4; q++) {
            float2 f = __half22float2(hp[q]);
            a[2 * q]     += f.x;
            a[2 * q + 1] += f.y;
        }
    }

#pragma unroll
    for (int q = 0; q < 8; q++) {
        a[q] += __shfl_xor_sync(0xffffffffu, a[q], 8);
        a[q] += __shfl_xor_sync(0xffffffffu, a[q], 16);
    }

    if (grp == 0) {
        float inv = 1.f / fmaxf((float)d, 1.f);
        union { __half2 h[4]; uint4 u; } pk;
        pk.h[0] = __floats2half2_rn(a[0] * inv, a[1] * inv);
        pk.h[1] = __floats2half2_rn(a[2] * inv, a[3] * inv);
        pk.h[2] = __floats2half2_rn(a[4] * inv, a[5] * inv);
        pk.h[3] = __floats2half2_rn(a[6] * inv, a[7] * inv);
        *(uint4*)&g_aggh[node * HID + sub * 8] = pk.u;
    }
}

// ---------------- launch ----------------------------------------------------
extern "C" void kernel_launch(void* const* d_in, const int* in_sizes, int n_in,
                              void* d_out, int out_size) {
    const float* x   = (const float*)d_in[0];
    const void*  ei  = d_in[1];
    const float* fcW = (const float*)d_in[3];
    const float* fcb = (const float*)d_in[4];
    const float* Wl1 = (const float*)d_in[5];
    const float* bl1 = (const float*)d_in[6];
    const float* Wr1 = (const float*)d_in[7];
    const float* Wl2 = (const float*)d_in[8];
    const float* bl2 = (const float*)d_in[9];
    const float* Wr2 = (const float*)d_in[10];
    const float* hW  = (const float*)d_in[11];
    const float* hb  = (const float*)d_in[12];

    int n  = in_sizes[0] / IN_DIM;
    int nE = in_sizes[1] / 2;
    float* out = (float*)d_out;

    __half* aggh; cudaGetSymbolAddress((void**)&aggh, g_aggh);
    __half* h0h;  cudaGetSymbolAddress((void**)&h0h, g_h0h);
    __half* h1h;  cudaGetSymbolAddress((void**)&h1h, g_h1h);

    int gbN  = (n + 255) / 256;
    int gbE  = (nE + 255) / 256;
    int nblk = (n + 511) / 512;
    int gbG  = (n + 127) / 128;
    int gbW  = (n + 7) / 8;

    // fork: CSR build on side stream, fc GEMM on main stream (independent)
    cudaStream_t st;
    cudaStreamCreateWithFlags(&st, cudaStreamNonBlocking);
    cudaEvent_t evFork, evJoin;
    cudaEventCreateWithFlags(&evFork, cudaEventDisableTiming);
    cudaEventCreateWithFlags(&evJoin, cudaEventDisableTiming);

    cudaEventRecord(evFork, 0);
    cudaStreamWaitEvent(st, evFork, 0);
    k_zs    <<<gbN, 256, 0, st>>>(ei, n, nE);
    k_count <<<gbE, 256, 0, st>>>(ei, n, nE);
    k_scan1 <<<nblk, 512, 0, st>>>(n);
    k_scan2 <<<1, 512, 0, st>>>(nblk);
    k_scan3 <<<nblk, 512, 0, st>>>(n);
    k_bucket<<<gbE, 256, 0, st>>>(ei, n, nE);
    cudaEventRecord(evJoin, st);

    // fc on main stream, concurrent with CSR build
    k_gemm  <<<gbG, 256>>>(x, x + 64, (const __half*)0, (const __half*)0,
                           fcW, fcW + 64, fcb,
                           h0h, (float*)0, hW, hb,
                           n, IN_DIM, 1);

    cudaStreamWaitEvent(0, evJoin, 0);   // join before aggregation

    k_agg  <<<gbW, 256>>>(0, n);
    k_gemm <<<gbG, 256>>>((const float*)0, (const float*)0, aggh, h0h,
                          Wl1, Wr1, bl1,
                          h1h, (float*)0, hW, hb,
                          n, HID, 1);
    k_agg  <<<gbW, 256>>>(1, n);
    k_gemm <<<gbG, 256>>>((const float*)0, (const float*)0, aggh, h1h,
                          Wl2, Wr2, bl2,
                          (__half*)0, out, hW, hb,
                          n, HID, 0);

    cudaEventDestroy(evFork);
    cudaEventDestroy(evJoin);
    cudaStreamDestroy(st);
}